// round 5
// baseline (speedup 1.0000x reference)
#include <cuda_runtime.h>

#define NB 8
#define NK 64
#define HW (1024*1024)
#define GRID 592          // 148 SMs x 4 blocks, single wave (co-resident)
#define BPI (GRID/NB)     // 74 blocks per image

// Scratch (device globals — no allocation allowed). Self-cleaned each launch.
// g_sumA[b*NK+k]: bits[24,64): fixed-point ch0 sum (scale 1024, bias +16384/add)
//                 bits[0,24):  pixel count
__device__ unsigned long long g_sumA[NB*NK];
__device__ unsigned int       g_sumB[NB*NK];
__device__ double             g_loss;
__device__ unsigned int       g_bar1, g_bar2;
__device__ unsigned char      g_seg8[(size_t)NB*HW];  // compressed masks (0..63)

__device__ __forceinline__ float sl1(float d) {
    float ad = fabsf(d);
    return ad < 1.f ? 0.5f*d*d : ad - 0.5f;
}

__global__ void __launch_bounds__(256, 4) fused_k(const float* __restrict__ pred,
                                                  const int* __restrict__ masks,
                                                  float* __restrict__ out) {
    const int b     = blockIdx.x & (NB-1);
    const int chunk = blockIdx.x >> 3;          // 0..BPI-1 within image b

    const float4* p0 = (const float4*)(pred + (size_t)b*2*HW);
    const float4* p1 = (const float4*)(pred + (size_t)b*2*HW + HW);
    const int4*   m  = (const int4*)(masks + (size_t)b*HW);
    uchar4*       s8 = (uchar4*)(g_seg8 + (size_t)b*HW);

    // ---------------- Phase 1: segment sums (per-warp packed histograms) ----
    __shared__ unsigned long long h1[8][NK];
    __shared__ unsigned int       h2[8][NK];
    {
        int w = threadIdx.x >> 5, l = threadIdx.x & 31;
        h1[w][l] = 0ull; h1[w][l+32] = 0ull;
        h2[w][l] = 0u;   h2[w][l+32] = 0u;
    }
    __syncthreads();
    unsigned long long* H1 = h1[threadIdx.x >> 5];
    unsigned int*       H2 = h2[threadIdx.x >> 5];

    const int nvec   = HW/4;
    const int stride = BPI*256;
    for (int v = chunk*256 + threadIdx.x; v < nvec; v += stride) {
        float4 a = p0[v];
        float4 c = p1[v];
        int4   s = __ldcs(&m[v]);   // read-once: evict-first, keep L2 for pred
        s8[v] = make_uchar4((unsigned char)s.x, (unsigned char)s.y,
                            (unsigned char)s.z, (unsigned char)s.w);
        unsigned qa0 = __float2uint_rn(fmaf(a.x, 1024.f, 16384.f));
        unsigned qa1 = __float2uint_rn(fmaf(a.y, 1024.f, 16384.f));
        unsigned qa2 = __float2uint_rn(fmaf(a.z, 1024.f, 16384.f));
        unsigned qa3 = __float2uint_rn(fmaf(a.w, 1024.f, 16384.f));
        unsigned qc0 = __float2uint_rn(fmaf(c.x, 1024.f, 16384.f));
        unsigned qc1 = __float2uint_rn(fmaf(c.y, 1024.f, 16384.f));
        unsigned qc2 = __float2uint_rn(fmaf(c.z, 1024.f, 16384.f));
        unsigned qc3 = __float2uint_rn(fmaf(c.w, 1024.f, 16384.f));
        atomicAdd(&H1[s.x], ((unsigned long long)qa0 << 24) | 1ull);
        atomicAdd(&H1[s.y], ((unsigned long long)qa1 << 24) | 1ull);
        atomicAdd(&H1[s.z], ((unsigned long long)qa2 << 24) | 1ull);
        atomicAdd(&H1[s.w], ((unsigned long long)qa3 << 24) | 1ull);
        atomicAdd(&H2[s.x], qc0);
        atomicAdd(&H2[s.y], qc1);
        atomicAdd(&H2[s.z], qc2);
        atomicAdd(&H2[s.w], qc3);
    }
    __syncthreads();

    if (threadIdx.x < NK) {
        unsigned long long tA = 0ull;
        unsigned int       tB = 0u;
        #pragma unroll
        for (int w = 0; w < 8; w++) { tA += h1[w][threadIdx.x]; tB += h2[w][threadIdx.x]; }
        atomicAdd(&g_sumA[b*NK + threadIdx.x], tA);
        atomicAdd(&g_sumB[b*NK + threadIdx.x], tB);
    }

    // ---------------- Grid barrier (all 592 blocks co-resident) ------------
    __threadfence();
    __syncthreads();
    if (threadIdx.x == 0) {
        atomicAdd(&g_bar1, 1u);
        volatile unsigned* p = &g_bar1;
        while (*p < GRID) __nanosleep(64);
    }
    __syncthreads();
    __threadfence();  // acquire: make all blocks' sums visible

    // ---------------- Means unpack -----------------------------------------
    __shared__ float mk0[NK], mk1[NK];
    if (threadIdx.x < NK) {
        int i = b*NK + threadIdx.x;
        unsigned long long A = g_sumA[i];
        long long n  = (long long)(A & 0xFFFFFFull);
        long long Q0 = (long long)(A >> 24);
        long long Q1 = (long long)g_sumB[i];
        float S0 = (float)(Q0 - n*16384ll) * (1.0f/1024.0f);
        float S1 = (float)(Q1 - n*16384ll) * (1.0f/1024.0f);
        float inv = 1.0f / ((float)n + 1e-8f);
        mk0[threadIdx.x] = S0 * inv;
        mk1[threadIdx.x] = S1 * inv;
    }
    __syncthreads();

    // ---------------- Phase 2: smooth-L1 vs means (pred from L2) -----------
    const uchar4* s8r = (const uchar4*)(g_seg8 + (size_t)b*HW);
    float acc = 0.f;
    int v = chunk*256 + threadIdx.x;
    for (; v + stride < nvec; v += 2*stride) {
        float4 a0 = p0[v],        c0 = p1[v];
        float4 a1 = p0[v+stride], c1 = p1[v+stride];
        uchar4 s0 = s8r[v];
        uchar4 s1 = s8r[v+stride];
        acc += sl1(a0.x - mk0[s0.x]) + sl1(c0.x - mk1[s0.x]);
        acc += sl1(a0.y - mk0[s0.y]) + sl1(c0.y - mk1[s0.y]);
        acc += sl1(a0.z - mk0[s0.z]) + sl1(c0.z - mk1[s0.z]);
        acc += sl1(a0.w - mk0[s0.w]) + sl1(c0.w - mk1[s0.w]);
        acc += sl1(a1.x - mk0[s1.x]) + sl1(c1.x - mk1[s1.x]);
        acc += sl1(a1.y - mk0[s1.y]) + sl1(c1.y - mk1[s1.y]);
        acc += sl1(a1.z - mk0[s1.z]) + sl1(c1.z - mk1[s1.z]);
        acc += sl1(a1.w - mk0[s1.w]) + sl1(c1.w - mk1[s1.w]);
    }
    for (; v < nvec; v += stride) {
        float4 a = p0[v], c = p1[v];
        uchar4 s = s8r[v];
        acc += sl1(a.x - mk0[s.x]) + sl1(c.x - mk1[s.x]);
        acc += sl1(a.y - mk0[s.y]) + sl1(c.y - mk1[s.y]);
        acc += sl1(a.z - mk0[s.z]) + sl1(c.z - mk1[s.z]);
        acc += sl1(a.w - mk0[s.w]) + sl1(c.w - mk1[s.w]);
    }

    #pragma unroll
    for (int o = 16; o; o >>= 1) acc += __shfl_down_sync(0xffffffffu, acc, o);
    __shared__ float ws[8];
    if ((threadIdx.x & 31) == 0) ws[threadIdx.x >> 5] = acc;
    __syncthreads();
    if (threadIdx.x == 0) {
        float s = 0.f;
        #pragma unroll
        for (int w = 0; w < 8; w++) s += ws[w];
        atomicAdd(&g_loss, (double)s);
    }

    // ---------------- Last block: finalize + self-clean ---------------------
    __threadfence();
    __shared__ int is_last;
    if (threadIdx.x == 0) is_last = (atomicAdd(&g_bar2, 1u) == GRID-1);
    __syncthreads();
    if (is_last) {
        for (int i = threadIdx.x; i < NB*NK; i += 256) { g_sumA[i] = 0ull; g_sumB[i] = 0u; }
        __syncthreads();
        if (threadIdx.x == 0) {
            double vv = g_loss / (double)((size_t)NB*2*HW);
            float r = (float)vv;
            if (isnan(r)) r = 0.f;
            out[0] = r;
            g_loss = 0.0;
            g_bar1 = 0u;
            g_bar2 = 0u;
            __threadfence();
        }
    }
}

extern "C" void kernel_launch(void* const* d_in, const int* in_sizes, int n_in,
                              void* d_out, int out_size) {
    const float* pred  = (const float*)d_in[0];
    // d_in[1] = ab_gt: only shape-checked in the reference; never read.
    const int*   masks = (const int*)d_in[2];
    fused_k<<<GRID, 256>>>(pred, masks, (float*)d_out);
}

// round 6
// speedup vs baseline: 1.0963x; 1.0963x over previous
#include <cuda_runtime.h>

#define NB 8
#define NK 64
#define HW (1024*1024)

// Scratch (device globals — zero at load; self-cleaned by pass2's last block)
__device__ unsigned int       g_cnt[NB*NK];
__device__ unsigned long long g_q0[NB*NK];   // sum of (round(512*v0)+4096)
__device__ unsigned long long g_q1[NB*NK];   // sum of (round(512*v1)+4096)
__device__ double             g_loss;
__device__ unsigned int       g_done;
__device__ unsigned char      g_seg8[(size_t)NB*HW];  // compressed masks (0..63)

__device__ __forceinline__ float sl1(float d) {
    float ad = fabsf(d);
    return ad < 1.f ? 0.5f*d*d : ad - 0.5f;
}

// Pass 1: ONE packed 64-bit smem atomic per pixel.
// word = (q0 << 36) | (q1 << 12) | 1
__global__ void __launch_bounds__(256) pass1_k(const float* __restrict__ pred,
                                               const int* __restrict__ masks) {
    const int b = blockIdx.y;
    const float4* p0 = (const float4*)(pred + (size_t)b*2*HW);
    const float4* p1 = (const float4*)(pred + (size_t)b*2*HW + HW);
    const int4*   m  = (const int4*)(masks + (size_t)b*HW);
    uchar4*       s8 = (uchar4*)(g_seg8 + (size_t)b*HW);

    __shared__ unsigned long long h[8][NK];   // per-warp packed histograms (4KB)
    {
        int w = threadIdx.x >> 5, l = threadIdx.x & 31;
        h[w][l] = 0ull; h[w][l+32] = 0ull;
    }
    __syncthreads();
    unsigned long long* H = h[threadIdx.x >> 5];

    const int nvec = HW/4;
    for (int v = blockIdx.x*blockDim.x + threadIdx.x; v < nvec; v += gridDim.x*blockDim.x) {
        float4 a = p0[v];
        float4 c = p1[v];
        int4   s = __ldcs(&m[v]);
        s8[v] = make_uchar4((unsigned char)s.x, (unsigned char)s.y,
                            (unsigned char)s.z, (unsigned char)s.w);
        unsigned long long qa0 = __float2uint_rn(fmaf(a.x, 512.f, 4096.f));
        unsigned long long qa1 = __float2uint_rn(fmaf(a.y, 512.f, 4096.f));
        unsigned long long qa2 = __float2uint_rn(fmaf(a.z, 512.f, 4096.f));
        unsigned long long qa3 = __float2uint_rn(fmaf(a.w, 512.f, 4096.f));
        unsigned long long qc0 = __float2uint_rn(fmaf(c.x, 512.f, 4096.f));
        unsigned long long qc1 = __float2uint_rn(fmaf(c.y, 512.f, 4096.f));
        unsigned long long qc2 = __float2uint_rn(fmaf(c.z, 512.f, 4096.f));
        unsigned long long qc3 = __float2uint_rn(fmaf(c.w, 512.f, 4096.f));
        atomicAdd(&H[s.x], (qa0 << 36) | (qc0 << 12) | 1ull);
        atomicAdd(&H[s.y], (qa1 << 36) | (qc1 << 12) | 1ull);
        atomicAdd(&H[s.z], (qa2 << 36) | (qc2 << 12) | 1ull);
        atomicAdd(&H[s.w], (qa3 << 36) | (qc3 << 12) | 1ull);
    }
    __syncthreads();

    // Unpack each warp's word BEFORE summing (fields would carry otherwise)
    if (threadIdx.x < NK) {
        unsigned int       cnt = 0;
        unsigned long long q0 = 0ull, q1 = 0ull;
        #pragma unroll
        for (int w = 0; w < 8; w++) {
            unsigned long long A = h[w][threadIdx.x];
            cnt += (unsigned int)(A & 0xFFFull);
            q1  += (A >> 12) & 0xFFFFFFull;
            q0  +=  A >> 36;
        }
        int i = b*NK + threadIdx.x;
        atomicAdd(&g_cnt[i], cnt);
        atomicAdd(&g_q0[i], q0);
        atomicAdd(&g_q1[i], q1);
    }
}

// Pass 2: unpack means, smooth-L1, global sum; last block finalizes + self-cleans
__global__ void __launch_bounds__(256) pass2_k(const float* __restrict__ pred,
                                               float* __restrict__ out,
                                               int nblocks) {
    const int b = blockIdx.y;
    __shared__ float mk0[NK], mk1[NK];
    if (threadIdx.x < NK) {
        int i = b*NK + threadIdx.x;
        long long n  = (long long)g_cnt[i];
        long long Q0 = (long long)g_q0[i];
        long long Q1 = (long long)g_q1[i];
        float S0 = (float)(Q0 - n*4096ll) * (1.0f/512.0f);
        float S1 = (float)(Q1 - n*4096ll) * (1.0f/512.0f);
        float inv = 1.0f / ((float)n + 1e-8f);
        mk0[threadIdx.x] = S0 * inv;
        mk1[threadIdx.x] = S1 * inv;
    }
    __syncthreads();

    const float4* p0 = (const float4*)(pred + (size_t)b*2*HW);
    const float4* p1 = (const float4*)(pred + (size_t)b*2*HW + HW);
    const uchar4* s8 = (const uchar4*)(g_seg8 + (size_t)b*HW);

    float acc = 0.f;
    const int nvec   = HW/4;
    const int stride = gridDim.x*blockDim.x;
    int v = blockIdx.x*blockDim.x + threadIdx.x;
    for (; v + stride < nvec; v += 2*stride) {
        float4 a0 = p0[v],        c0 = p1[v];
        float4 a1 = p0[v+stride], c1 = p1[v+stride];
        uchar4 s0 = s8[v];
        uchar4 s1 = s8[v+stride];
        acc += sl1(a0.x - mk0[s0.x]) + sl1(c0.x - mk1[s0.x]);
        acc += sl1(a0.y - mk0[s0.y]) + sl1(c0.y - mk1[s0.y]);
        acc += sl1(a0.z - mk0[s0.z]) + sl1(c0.z - mk1[s0.z]);
        acc += sl1(a0.w - mk0[s0.w]) + sl1(c0.w - mk1[s0.w]);
        acc += sl1(a1.x - mk0[s1.x]) + sl1(c1.x - mk1[s1.x]);
        acc += sl1(a1.y - mk0[s1.y]) + sl1(c1.y - mk1[s1.y]);
        acc += sl1(a1.z - mk0[s1.z]) + sl1(c1.z - mk1[s1.z]);
        acc += sl1(a1.w - mk0[s1.w]) + sl1(c1.w - mk1[s1.w]);
    }
    for (; v < nvec; v += stride) {
        float4 a = p0[v], c = p1[v];
        uchar4 s = s8[v];
        acc += sl1(a.x - mk0[s.x]) + sl1(c.x - mk1[s.x]);
        acc += sl1(a.y - mk0[s.y]) + sl1(c.y - mk1[s.y]);
        acc += sl1(a.z - mk0[s.z]) + sl1(c.z - mk1[s.z]);
        acc += sl1(a.w - mk0[s.w]) + sl1(c.w - mk1[s.w]);
    }

    #pragma unroll
    for (int o = 16; o; o >>= 1) acc += __shfl_down_sync(0xffffffffu, acc, o);
    __shared__ float ws[8];
    if ((threadIdx.x & 31) == 0) ws[threadIdx.x >> 5] = acc;
    __syncthreads();
    if (threadIdx.x == 0) {
        float s = 0.f;
        #pragma unroll
        for (int w = 0; w < 8; w++) s += ws[w];
        atomicAdd(&g_loss, (double)s);
    }

    // Elect the last-finishing block to finalize + clean for next replay
    __threadfence();
    __shared__ int is_last;
    if (threadIdx.x == 0) is_last = (atomicAdd(&g_done, 1u) == (unsigned)(nblocks-1));
    __syncthreads();
    if (is_last) {
        for (int i = threadIdx.x; i < NB*NK; i += 256) {
            g_cnt[i] = 0u; g_q0[i] = 0ull; g_q1[i] = 0ull;
        }
        if (threadIdx.x == 0) {
            double vv = g_loss / (double)((size_t)NB*2*HW);
            float r = (float)vv;
            if (isnan(r)) r = 0.f;
            out[0] = r;
            g_loss = 0.0;
            g_done = 0u;
            __threadfence();
        }
    }
}

extern "C" void kernel_launch(void* const* d_in, const int* in_sizes, int n_in,
                              void* d_out, int out_size) {
    const float* pred  = (const float*)d_in[0];
    // d_in[1] = ab_gt: only shape-checked in the reference; never read.
    const int*   masks = (const int*)d_in[2];

    pass1_k<<<dim3(148, NB), 256>>>(pred, masks);
    pass2_k<<<dim3(148, NB), 256>>>(pred, (float*)d_out, 148*NB);
}

// round 9
// speedup vs baseline: 1.1053x; 1.0082x over previous
#include <cuda_runtime.h>

#define NB 8
#define NK 64
#define HW (1024*1024)

// Scratch (device globals — zero at load; self-cleaned by pass2's last block)
__device__ unsigned int       g_cnt[NB*NK];
__device__ unsigned long long g_q0[NB*NK];
__device__ unsigned long long g_q1[NB*NK];
__device__ double             g_loss;
__device__ unsigned int       g_done;
__device__ unsigned char      g_seg8[(size_t)NB*HW];  // compressed masks (0..63)

__device__ __forceinline__ float sl1(float d) {
    float ad = fabsf(d);
    return ad < 1.f ? 0.5f*d*d : ad - 0.5f;
}

// Pass 1: one packed 64-bit smem atomic per pixel; masks streamed (read-once).
// word = (q0 << 36) | (q1 << 12) | 1,  q = round(512*v)+4096
__global__ void __launch_bounds__(256) pass1_k(const float* __restrict__ pred,
                                               const int* __restrict__ masks) {
    const int b = blockIdx.y;
    const float4* p0 = (const float4*)(pred + (size_t)b*2*HW);
    const float4* p1 = (const float4*)(pred + (size_t)b*2*HW + HW);
    const int4*   m  = (const int4*)(masks + (size_t)b*HW);
    unsigned*     s8 = (unsigned*)(g_seg8 + (size_t)b*HW);

    __shared__ unsigned long long h[8][NK];   // per-warp packed histograms (4KB)
    {
        int w = threadIdx.x >> 5, l = threadIdx.x & 31;
        h[w][l] = 0ull; h[w][l+32] = 0ull;
    }
    __syncthreads();
    unsigned long long* H = h[threadIdx.x >> 5];

    const int nvec = HW/4;
    for (int v = blockIdx.x*blockDim.x + threadIdx.x; v < nvec; v += gridDim.x*blockDim.x) {
        float4 a = p0[v];
        float4 c = p1[v];
        int4   s = __ldcs(&m[v]);
        unsigned packed = (unsigned)(s.x & 0xFF) | ((unsigned)(s.y & 0xFF) << 8)
                        | ((unsigned)(s.z & 0xFF) << 16) | ((unsigned)(s.w & 0xFF) << 24);
        s8[v] = packed;
        unsigned long long qa0 = __float2uint_rn(fmaf(a.x, 512.f, 4096.f));
        unsigned long long qa1 = __float2uint_rn(fmaf(a.y, 512.f, 4096.f));
        unsigned long long qa2 = __float2uint_rn(fmaf(a.z, 512.f, 4096.f));
        unsigned long long qa3 = __float2uint_rn(fmaf(a.w, 512.f, 4096.f));
        unsigned long long qc0 = __float2uint_rn(fmaf(c.x, 512.f, 4096.f));
        unsigned long long qc1 = __float2uint_rn(fmaf(c.y, 512.f, 4096.f));
        unsigned long long qc2 = __float2uint_rn(fmaf(c.z, 512.f, 4096.f));
        unsigned long long qc3 = __float2uint_rn(fmaf(c.w, 512.f, 4096.f));
        atomicAdd(&H[s.x], (qa0 << 36) | (qc0 << 12) | 1ull);
        atomicAdd(&H[s.y], (qa1 << 36) | (qc1 << 12) | 1ull);
        atomicAdd(&H[s.z], (qa2 << 36) | (qc2 << 12) | 1ull);
        atomicAdd(&H[s.w], (qa3 << 36) | (qc3 << 12) | 1ull);
    }
    __syncthreads();

    // Unpack each warp's word BEFORE summing (fields would carry otherwise)
    if (threadIdx.x < NK) {
        unsigned int       cnt = 0;
        unsigned long long q0 = 0ull, q1 = 0ull;
        #pragma unroll
        for (int w = 0; w < 8; w++) {
            unsigned long long A = h[w][threadIdx.x];
            cnt += (unsigned int)(A & 0xFFFull);
            q1  += (A >> 12) & 0xFFFFFFull;
            q0  +=  A >> 36;
        }
        int i = b*NK + threadIdx.x;
        atomicAdd(&g_cnt[i], cnt);
        atomicAdd(&g_q0[i], q0);
        atomicAdd(&g_q1[i], q1);
    }
}

// Pass 2: unpack means, smooth-L1, global sum; last block finalizes + self-cleans
__global__ void __launch_bounds__(256) pass2_k(const float* __restrict__ pred,
                                               float* __restrict__ out,
                                               int nblocks) {
    const int b = blockIdx.y;
    __shared__ float mk0[NK], mk1[NK];
    if (threadIdx.x < NK) {
        int i = b*NK + threadIdx.x;
        long long n  = (long long)g_cnt[i];
        long long Q0 = (long long)g_q0[i];
        long long Q1 = (long long)g_q1[i];
        float S0 = (float)(Q0 - n*4096ll) * (1.0f/512.0f);
        float S1 = (float)(Q1 - n*4096ll) * (1.0f/512.0f);
        float inv = 1.0f / ((float)n + 1e-8f);
        mk0[threadIdx.x] = S0 * inv;
        mk1[threadIdx.x] = S1 * inv;
    }
    __syncthreads();

    const float4* p0 = (const float4*)(pred + (size_t)b*2*HW);
    const float4* p1 = (const float4*)(pred + (size_t)b*2*HW + HW);
    const uchar4* s8 = (const uchar4*)(g_seg8 + (size_t)b*HW);

    float acc = 0.f;
    const int nvec = HW/4;
    for (int v = blockIdx.x*blockDim.x + threadIdx.x; v < nvec; v += gridDim.x*blockDim.x) {
        float4 a = p0[v], c = p1[v];
        uchar4 s = s8[v];
        acc += sl1(a.x - mk0[s.x]) + sl1(c.x - mk1[s.x]);
        acc += sl1(a.y - mk0[s.y]) + sl1(c.y - mk1[s.y]);
        acc += sl1(a.z - mk0[s.z]) + sl1(c.z - mk1[s.z]);
        acc += sl1(a.w - mk0[s.w]) + sl1(c.w - mk1[s.w]);
    }

    #pragma unroll
    for (int o = 16; o; o >>= 1) acc += __shfl_down_sync(0xffffffffu, acc, o);
    __shared__ float ws[8];
    if ((threadIdx.x & 31) == 0) ws[threadIdx.x >> 5] = acc;
    __syncthreads();

    __shared__ int is_last;
    if (threadIdx.x == 0) {
        float s = 0.f;
        #pragma unroll
        for (int w = 0; w < 8; w++) s += ws[w];
        atomicAdd(&g_loss, (double)s);
        __threadfence();   // order my g_loss add before my g_done add (thread 0 only)
        is_last = (atomicAdd(&g_done, 1u) == (unsigned)(nblocks-1));
    }
    __syncthreads();
    if (is_last) {
        for (int i = threadIdx.x; i < NB*NK; i += 256) {
            g_cnt[i] = 0u; g_q0[i] = 0ull; g_q1[i] = 0ull;
        }
        if (threadIdx.x == 0) {
            double vv = g_loss / (double)((size_t)NB*2*HW);
            float r = (float)vv;
            if (isnan(r)) r = 0.f;
            out[0] = r;
            g_loss = 0.0;
            g_done = 0u;
            __threadfence();
        }
    }
}

extern "C" void kernel_launch(void* const* d_in, const int* in_sizes, int n_in,
                              void* d_out, int out_size) {
    const float* pred  = (const float*)d_in[0];
    // d_in[1] = ab_gt: only shape-checked in the reference; never read.
    const int*   masks = (const int*)d_in[2];

    pass1_k<<<dim3(148, NB), 256>>>(pred, masks);
    pass2_k<<<dim3(148, NB), 256>>>(pred, (float*)d_out, 148*NB);
}